// round 16
// baseline (speedup 1.0000x reference)
#include <cuda_runtime.h>
#include <cuda_fp16.h>
#include <cstdint>

#define B_    32
#define M_    512
#define S_    10
#define V_    32000
#define D_    128

#define GBLK  2048            // 512 thr, 8 m per block, 2 warps/m; 64 blocks/batch
#define GPB   64              // gather blocks per batch
#define FSPL  16              // F-capable blocks per batch (q % 4 == 0), 32 m each

// Bags for tables 1..3 in fp16, packed 4 dims per uint2.
__device__ __align__(16) uint2 g_bagh[3u * B_ * M_ * (D_ / 4)];   // 12.6 MB
__device__ __align__(16) float g_part0[GBLK * D_];       // hop-0 partials
__device__ float g_den0[GBLK];
__device__ __align__(16) float g_part1[B_ * FSPL * D_];  // hop-1 partials
__device__ float g_den1[B_ * FSPL];
__device__ __align__(16) float g_part2[B_ * FSPL * D_];  // hop-2 partials
__device__ float g_den2[B_ * FSPL];
// Per-batch monotonic tickets (never reset; replay-safe).
__device__ unsigned int g_tA[B_];   // 64 arrivals / replay (gather done)
__device__ unsigned int g_tB[B_];   // 16 arrivals / replay (hop-1 done)
__device__ unsigned int g_tC[B_];   // 16 arrivals / replay (hop-2 done)

__device__ __forceinline__ float warpSum(float v) {
    #pragma unroll
    for (int o = 16; o > 0; o >>= 1) v += __shfl_xor_sync(0xffffffffu, v, o);
    return v;
}
__device__ __forceinline__ uint2 pack4(float4 v) {
    __half2 lo = __floats2half2_rn(v.x, v.y);
    __half2 hi = __floats2half2_rn(v.z, v.w);
    uint2 r;
    r.x = *reinterpret_cast<unsigned*>(&lo);
    r.y = *reinterpret_cast<unsigned*>(&hi);
    return r;
}
__device__ __forceinline__ float4 unpack4(uint2 p) {
    __half2 lo = *reinterpret_cast<__half2*>(&p.x);
    __half2 hi = *reinterpret_cast<__half2*>(&p.y);
    float2 l = __half22float2(lo);
    float2 h = __half22float2(hi);
    return make_float4(l.x, l.y, h.x, h.y);
}

// ---------------------------------------------------------------------------
// Fused kernel. Part 1 (all 2048 blocks): gather, R8/R13 shape unchanged.
// Part 2 (16 blocks per batch, q%4==0): hops 1+2 with per-batch tickets.
// Early batches' part-2 overlaps late batches' part-1.
// ---------------------------------------------------------------------------
__global__ void __launch_bounds__(512, 2)
k_all(const int* __restrict__ story, const float* __restrict__ hidden,
      const float* __restrict__ C, float* __restrict__ out)
{
    __shared__ __align__(16) float s_pt[16][D_];
    __shared__ float s_den[16];
    __shared__ __align__(16) float s_n[4][D_];
    __shared__ float s_dn[4];
    __shared__ __align__(16) float s_u[D_];
    __shared__ int s_last;

    const int tid  = threadIdx.x;
    const int lane = tid & 31;
    const int wid  = tid >> 5;          // 0..15
    const int b    = blockIdx.x >> 6;   // / GPB
    const int q    = blockIdx.x & 63;   // gather slot within batch

    // ======================= Part 1: gather (unchanged shape) ===============
    {
        const bool isX = (wid < 8);
        const int  ml  = wid & 7;               // m-local 0..7
        const int  m   = q * 8 + ml;

        int tok = 0;
        if (lane < S_) tok = story[((size_t)b * M_ + m) * S_ + lane];

        const float4* C4 = reinterpret_cast<const float4*>(C);
        const size_t tabstr = (size_t)V_ * (D_ / 4);
        const float4* base0 = C4 + (isX ? 0 : 2) * tabstr;   // C0 or C2

        float4 a0 = make_float4(0.f, 0.f, 0.f, 0.f);
        float4 a1 = a0;
        #pragma unroll
        for (int s = 0; s < S_; s++) {
            const int t = __shfl_sync(0xffffffffu, tok, s);
            const size_t idx = (size_t)t * (D_ / 4) + lane;
            const float4 r0 = base0[idx];
            const float4 r1 = base0[idx + tabstr];
            a0.x += r0.x; a0.y += r0.y; a0.z += r0.z; a0.w += r0.w;
            a1.x += r1.x; a1.y += r1.y; a1.z += r1.z; a1.w += r1.w;
        }

        const size_t row  = ((size_t)b * M_ + m) * (D_ / 4) + lane;
        const size_t bstr = (size_t)B_ * M_ * (D_ / 4);

        if (isX) {
            const float4 u4 = reinterpret_cast<const float4*>(hidden + (size_t)b * D_)[lane];
            float d = a0.x * u4.x + a0.y * u4.y + a0.z * u4.z + a0.w * u4.w;
            d = warpSum(d);
            const float e = __expf(d);
            reinterpret_cast<float4*>(&s_pt[ml][0])[lane] =
                make_float4(e * a1.x, e * a1.y, e * a1.z, e * a1.w);
            if (lane == 0) s_den[ml] = e;
            g_bagh[row] = pack4(a1);                 // table C1
        } else {
            g_bagh[row + bstr]     = pack4(a0);      // table C2
            g_bagh[row + 2 * bstr] = pack4(a1);      // table C3
        }

        __syncthreads();
        if (tid < D_) {
            float v = 0.f;
            #pragma unroll
            for (int k = 0; k < 8; k++) v += s_pt[k][tid];
            g_part0[(size_t)blockIdx.x * D_ + tid] = v;
        }
        if (tid == 0) {
            float dn = 0.f;
            #pragma unroll
            for (int k = 0; k < 8; k++) dn += s_den[k];
            g_den0[blockIdx.x] = dn;
        }
    }

    // ---- publish gather results, arrive on per-batch ticket A ----
    __threadfence();
    __syncthreads();
    if ((q & 3) != 0) {
        if (tid == 0) atomicAdd(&g_tA[b], 1u);
        return;                                   // 48/64 blocks free their SM
    }
    if (tid == 0) {
        const unsigned a = atomicAdd(&g_tA[b], 1u) + 1u;
        const unsigned target = ((a + GPB - 1u) / GPB) * GPB;
        while (*((volatile unsigned*)&g_tA[b]) < target) __nanosleep(32);
    }
    __syncthreads();
    __threadfence();

    // ======================= Part 2: hops 1+2 (16 blocks/batch) =============
    const int sp = q >> 2;                        // 0..15, covers m [sp*32, sp*32+32)
    const size_t bstr = (size_t)B_ * M_ * (D_ / 4);

    // ---- u1 = hidden + reduce64(part0): 4 threads/dim x 16 partials ----
    {
        const int dim = tid & 127;
        const int qt  = tid >> 7;                 // 0..3
        float dn = 0.f, num = 0.f;
        #pragma unroll 4
        for (int k = qt * 16; k < qt * 16 + 16; k++) {
            dn  += g_den0[b * GPB + k];
            num += g_part0[((size_t)b * GPB + k) * D_ + dim];
        }
        s_n[qt][dim] = num;
        if (dim == 0) s_dn[qt] = dn;
    }
    __syncthreads();
    if (tid < D_) {
        s_u[tid] = hidden[(size_t)b * D_ + tid]
                 + (s_n[0][tid] + s_n[1][tid] + s_n[2][tid] + s_n[3][tid])
                   / (s_dn[0] + s_dn[1] + s_dn[2] + s_dn[3]);
    }
    __syncthreads();

    // ---- hop-1 pass: 16 warps x 2 m (C1 -> logit, C2 -> num) ----
    {
        const float4 u4 = reinterpret_cast<const float4*>(s_u)[lane];
        float4 acc = make_float4(0.f, 0.f, 0.f, 0.f);
        float den = 0.f;
        #pragma unroll
        for (int i = 0; i < 2; i++) {
            const size_t r = ((size_t)(b * M_ + sp * 32 + wid * 2 + i)) * (D_ / 4) + lane;
            const float4 va = unpack4(g_bagh[r]);               // C1
            const float4 vb = unpack4(g_bagh[bstr + r]);        // C2
            float d = va.x * u4.x + va.y * u4.y + va.z * u4.z + va.w * u4.w;
            d = warpSum(d);
            const float e = __expf(d);
            acc.x += e * vb.x; acc.y += e * vb.y;
            acc.z += e * vb.z; acc.w += e * vb.w;
            den += e;
        }
        reinterpret_cast<float4*>(&s_pt[wid][0])[lane] = acc;
        if (lane == 0) s_den[wid] = den;
    }
    __syncthreads();
    if (tid < D_) {
        float v = 0.f;
        #pragma unroll
        for (int k = 0; k < 16; k++) v += s_pt[k][tid];
        g_part1[((size_t)b * FSPL + sp) * D_ + tid] = v;
    }
    if (tid == 0) {
        float dn = 0.f;
        #pragma unroll
        for (int k = 0; k < 16; k++) dn += s_den[k];
        g_den1[b * FSPL + sp] = dn;
    }

    // ---- per-batch barrier B (16 arrivals) ----
    __threadfence();
    __syncthreads();
    if (tid == 0) {
        const unsigned a = atomicAdd(&g_tB[b], 1u) + 1u;
        const unsigned target = ((a + FSPL - 1u) / FSPL) * FSPL;
        while (*((volatile unsigned*)&g_tB[b]) < target) __nanosleep(32);
    }
    __syncthreads();
    __threadfence();

    // ---- u2 = u1 + reduce16(part1): 4 threads/dim x 4 partials ----
    {
        const int dim = tid & 127;
        const int qt  = tid >> 7;
        float dn = 0.f, num = 0.f;
        #pragma unroll
        for (int k = qt * 4; k < qt * 4 + 4; k++) {
            dn  += g_den1[b * FSPL + k];
            num += g_part1[((size_t)b * FSPL + k) * D_ + dim];
        }
        s_n[qt][dim] = num;
        if (dim == 0) s_dn[qt] = dn;
    }
    __syncthreads();
    if (tid < D_) {
        s_u[tid] += (s_n[0][tid] + s_n[1][tid] + s_n[2][tid] + s_n[3][tid])
                  / (s_dn[0] + s_dn[1] + s_dn[2] + s_dn[3]);
    }
    __syncthreads();

    // ---- hop-2 pass: logits -> OUT; partials for u3 (C2 -> logit, C3 -> num)
    {
        const float4 u4 = reinterpret_cast<const float4*>(s_u)[lane];
        float4 acc = make_float4(0.f, 0.f, 0.f, 0.f);
        float den = 0.f;
        #pragma unroll
        for (int i = 0; i < 2; i++) {
            const int m = sp * 32 + wid * 2 + i;
            const size_t r = ((size_t)(b * M_ + m)) * (D_ / 4) + lane;
            const float4 va = unpack4(g_bagh[bstr + r]);        // C2
            const float4 vb = unpack4(g_bagh[2 * bstr + r]);    // C3
            float d = va.x * u4.x + va.y * u4.y + va.z * u4.z + va.w * u4.w;
            d = warpSum(d);
            const float e = __expf(d);
            if (lane == 0) out[(size_t)b * M_ + m] = d;         // prob_logit
            acc.x += e * vb.x; acc.y += e * vb.y;
            acc.z += e * vb.z; acc.w += e * vb.w;
            den += e;
        }
        reinterpret_cast<float4*>(&s_pt[wid][0])[lane] = acc;
        if (lane == 0) s_den[wid] = den;
    }
    __syncthreads();
    if (tid < D_) {
        float v = 0.f;
        #pragma unroll
        for (int k = 0; k < 16; k++) v += s_pt[k][tid];
        g_part2[((size_t)b * FSPL + sp) * D_ + tid] = v;
    }
    if (tid == 0) {
        float dn = 0.f;
        #pragma unroll
        for (int k = 0; k < 16; k++) dn += s_den[k];
        g_den2[b * FSPL + sp] = dn;
    }
    __syncthreads();

    // ---- last-arriver (mod-16, monotonic) computes final u3 -> OUT ----
    if (tid == 0) {
        __threadfence();
        const unsigned a = atomicAdd(&g_tC[b], 1u) + 1u;
        s_last = ((a % FSPL) == 0u);
    }
    __syncthreads();
    if (s_last) {
        __threadfence();   // acquire peers' partial writes
        if (tid < D_) {
            float dn = 0.f;
            #pragma unroll
            for (int k = 0; k < FSPL; k++) dn += g_den2[b * FSPL + k];
            float num = 0.f;
            #pragma unroll
            for (int k = 0; k < FSPL; k++) num += g_part2[((size_t)b * FSPL + k) * D_ + tid];
            out[(size_t)B_ * M_ + (size_t)b * D_ + tid] = s_u[tid] + num / dn;
        }
    }
}

extern "C" void kernel_launch(void* const* d_in, const int* in_sizes, int n_in,
                              void* d_out, int out_size)
{
    const int*   story  = (const int*)  d_in[0];   // [B, M, S] int32
    const float* hidden = (const float*)d_in[1];   // [B, 1, D] f32
    const float* C      = (const float*)d_in[2];   // [4, V, D] f32
    float* out = (float*)d_out;                    // [B*M] logits ++ [B*D] u

    k_all<<<GBLK, 512>>>(story, hidden, C, out);   // everything, one launch
}

// round 17
// speedup vs baseline: 1.1746x; 1.1746x over previous
#include <cuda_runtime.h>
#include <cuda_fp16.h>
#include <cstdint>

#define B_    32
#define M_    512
#define S_    10
#define V_    32000
#define D_    128

#define GBLK  2048            // gather blocks: 512 thr, 8 m per block, 2 warps/m
#define GPB   64              // gather blocks per batch
#define FSPL  16              // F blocks per batch, 32 m each
#define FBLK  (B_ * FSPL)     // 512 F blocks, appended after gather blocks

// Bags for tables 1..3 in fp16, packed 4 dims per uint2.
__device__ __align__(16) uint2 g_bagh[3u * B_ * M_ * (D_ / 4)];   // 12.6 MB
__device__ __align__(16) float g_part0[GBLK * D_];       // hop-0 partials
__device__ float g_den0[GBLK];
__device__ __align__(16) float g_part1[FBLK * D_];       // hop-1 partials
__device__ float g_den1[FBLK];
__device__ __align__(16) float g_part2[FBLK * D_];       // hop-2 partials
__device__ float g_den2[FBLK];
// Per-batch monotonic tickets (never reset; replay-safe).
__device__ unsigned int g_tA[B_];   // gather arrivals: +64 per batch per replay
__device__ unsigned int g_tF[B_];   // F-block round claim: +16 per batch per replay
__device__ unsigned int g_tB[B_];   // hop-1 done: +16 per batch per replay
__device__ unsigned int g_tC[B_];   // hop-2 done: +16 per batch per replay

__device__ __forceinline__ float warpSum(float v) {
    #pragma unroll
    for (int o = 16; o > 0; o >>= 1) v += __shfl_xor_sync(0xffffffffu, v, o);
    return v;
}
__device__ __forceinline__ uint2 pack4(float4 v) {
    __half2 lo = __floats2half2_rn(v.x, v.y);
    __half2 hi = __floats2half2_rn(v.z, v.w);
    uint2 r;
    r.x = *reinterpret_cast<unsigned*>(&lo);
    r.y = *reinterpret_cast<unsigned*>(&hi);
    return r;
}
__device__ __forceinline__ float4 unpack4(uint2 p) {
    __half2 lo = *reinterpret_cast<__half2*>(&p.x);
    __half2 hi = *reinterpret_cast<__half2*>(&p.y);
    float2 l = __half22float2(lo);
    float2 h = __half22float2(hi);
    return make_float4(l.x, l.y, h.x, h.y);
}

// ---------------------------------------------------------------------------
// One kernel, two block roles.
//   blocks [0, 2048): gather — R8/R13 shape, NEVER waits, arrives + exits.
//   blocks [2048, 2560): F — per-batch hops 1+2; dispatched only as gather
//   blocks retire (index-order), so gather keeps full occupancy.
// ---------------------------------------------------------------------------
__global__ void __launch_bounds__(512, 3)
k_all(const int* __restrict__ story, const float* __restrict__ hidden,
      const float* __restrict__ C, float* __restrict__ out)
{
    __shared__ __align__(16) float s_pt[16][D_];
    __shared__ float s_den[16];
    __shared__ __align__(16) float s_n[4][D_];
    __shared__ float s_dn[4];
    __shared__ __align__(16) float s_u[D_];
    __shared__ unsigned s_round;
    __shared__ int s_last;

    const int tid  = threadIdx.x;
    const int lane = tid & 31;
    const int wid  = tid >> 5;          // 0..15
    const size_t bstr = (size_t)B_ * M_ * (D_ / 4);
    const float4* C4 = reinterpret_cast<const float4*>(C);
    const size_t tabstr = (size_t)V_ * (D_ / 4);

    if (blockIdx.x < GBLK) {
        // =================== GATHER role (R8-identical shape) ===============
        const int b = blockIdx.x >> 6;
        const int q = blockIdx.x & 63;
        const bool isX = (wid < 8);
        const int  ml  = wid & 7;
        const int  m   = q * 8 + ml;

        int tok = 0;
        if (lane < S_) tok = story[((size_t)b * M_ + m) * S_ + lane];

        const float4* base0 = C4 + (isX ? 0 : 2) * tabstr;   // C0 or C2
        float4 a0 = make_float4(0.f, 0.f, 0.f, 0.f);
        float4 a1 = a0;
        #pragma unroll
        for (int s = 0; s < S_; s++) {
            const int t = __shfl_sync(0xffffffffu, tok, s);
            const size_t idx = (size_t)t * (D_ / 4) + lane;
            const float4 r0 = base0[idx];
            const float4 r1 = base0[idx + tabstr];
            a0.x += r0.x; a0.y += r0.y; a0.z += r0.z; a0.w += r0.w;
            a1.x += r1.x; a1.y += r1.y; a1.z += r1.z; a1.w += r1.w;
        }

        const size_t row = ((size_t)b * M_ + m) * (D_ / 4) + lane;
        if (isX) {
            const float4 u4 = reinterpret_cast<const float4*>(hidden + (size_t)b * D_)[lane];
            float d = a0.x * u4.x + a0.y * u4.y + a0.z * u4.z + a0.w * u4.w;
            d = warpSum(d);
            const float e = __expf(d);
            reinterpret_cast<float4*>(&s_pt[ml][0])[lane] =
                make_float4(e * a1.x, e * a1.y, e * a1.z, e * a1.w);
            if (lane == 0) s_den[ml] = e;
            g_bagh[row] = pack4(a1);                 // table C1
        } else {
            g_bagh[row + bstr]     = pack4(a0);      // table C2
            g_bagh[row + 2 * bstr] = pack4(a1);      // table C3
        }

        __syncthreads();
        if (tid < D_) {
            float v = 0.f;
            #pragma unroll
            for (int k = 0; k < 8; k++) v += s_pt[k][tid];
            g_part0[(size_t)blockIdx.x * D_ + tid] = v;
        }
        if (tid == 0) {
            float dn = 0.f;
            #pragma unroll
            for (int k = 0; k < 8; k++) dn += s_den[k];
            g_den0[blockIdx.x] = dn;
        }
        // publish + arrive (never waits)
        __threadfence();
        __syncthreads();
        if (tid == 0) atomicAdd(&g_tA[b], 1u);
        return;
    }

    // ======================= F role: hops 1+2 ==============================
    const int f  = blockIdx.x - GBLK;    // 0..511
    const int b  = f >> 4;               // / FSPL
    const int sp = f & (FSPL - 1);       // m-slice [sp*32, sp*32+32)

    // Claim replay round, wait for this batch's 64 gather arrivals of it.
    if (tid == 0) {
        const unsigned r = atomicAdd(&g_tF[b], 1u);
        const unsigned round = r / FSPL;             // replay index
        const unsigned target = (round + 1u) * GPB;
        while (*((volatile unsigned*)&g_tA[b]) < target) __nanosleep(64);
    }
    __syncthreads();
    __threadfence();

    // ---- u1 = hidden + reduce64(part0): 4 threads/dim x 16 partials ----
    {
        const int dim = tid & 127;
        const int qt  = tid >> 7;                    // 0..3
        float dn = 0.f, num = 0.f;
        #pragma unroll 4
        for (int k = qt * 16; k < qt * 16 + 16; k++) {
            dn  += g_den0[b * GPB + k];
            num += g_part0[((size_t)b * GPB + k) * D_ + dim];
        }
        s_n[qt][dim] = num;
        if (dim == 0) s_dn[qt] = dn;
    }
    __syncthreads();
    if (tid < D_) {
        s_u[tid] = hidden[(size_t)b * D_ + tid]
                 + (s_n[0][tid] + s_n[1][tid] + s_n[2][tid] + s_n[3][tid])
                   / (s_dn[0] + s_dn[1] + s_dn[2] + s_dn[3]);
    }
    __syncthreads();

    // ---- hop-1 pass: 16 warps x 2 m (C1 -> logit, C2 -> num) ----
    {
        const float4 u4 = reinterpret_cast<const float4*>(s_u)[lane];
        float4 acc = make_float4(0.f, 0.f, 0.f, 0.f);
        float den = 0.f;
        #pragma unroll
        for (int i = 0; i < 2; i++) {
            const size_t r = ((size_t)(b * M_ + sp * 32 + wid * 2 + i)) * (D_ / 4) + lane;
            const float4 va = unpack4(g_bagh[r]);               // C1
            const float4 vb = unpack4(g_bagh[bstr + r]);        // C2
            float d = va.x * u4.x + va.y * u4.y + va.z * u4.z + va.w * u4.w;
            d = warpSum(d);
            const float e = __expf(d);
            acc.x += e * vb.x; acc.y += e * vb.y;
            acc.z += e * vb.z; acc.w += e * vb.w;
            den += e;
        }
        reinterpret_cast<float4*>(&s_pt[wid][0])[lane] = acc;
        if (lane == 0) s_den[wid] = den;
    }
    __syncthreads();
    if (tid < D_) {
        float v = 0.f;
        #pragma unroll
        for (int k = 0; k < 16; k++) v += s_pt[k][tid];
        g_part1[((size_t)b * FSPL + sp) * D_ + tid] = v;
    }
    if (tid == 0) {
        float dn = 0.f;
        #pragma unroll
        for (int k = 0; k < 16; k++) dn += s_den[k];
        g_den1[b * FSPL + sp] = dn;
    }

    // ---- per-batch barrier B (16 arrivals, monotonic) ----
    __threadfence();
    __syncthreads();
    if (tid == 0) {
        const unsigned a = atomicAdd(&g_tB[b], 1u) + 1u;
        const unsigned target = ((a + FSPL - 1u) / FSPL) * FSPL;
        while (*((volatile unsigned*)&g_tB[b]) < target) __nanosleep(32);
    }
    __syncthreads();
    __threadfence();

    // ---- u2 = u1 + reduce16(part1): 4 threads/dim x 4 partials ----
    {
        const int dim = tid & 127;
        const int qt  = tid >> 7;
        float dn = 0.f, num = 0.f;
        #pragma unroll
        for (int k = qt * 4; k < qt * 4 + 4; k++) {
            dn  += g_den1[b * FSPL + k];
            num += g_part1[((size_t)b * FSPL + k) * D_ + dim];
        }
        s_n[qt][dim] = num;
        if (dim == 0) s_dn[qt] = dn;
    }
    __syncthreads();
    if (tid < D_) {
        s_u[tid] += (s_n[0][tid] + s_n[1][tid] + s_n[2][tid] + s_n[3][tid])
                  / (s_dn[0] + s_dn[1] + s_dn[2] + s_dn[3]);
    }
    __syncthreads();

    // ---- hop-2 pass: logits -> OUT; partials for u3 ----
    {
        const float4 u4 = reinterpret_cast<const float4*>(s_u)[lane];
        float4 acc = make_float4(0.f, 0.f, 0.f, 0.f);
        float den = 0.f;
        #pragma unroll
        for (int i = 0; i < 2; i++) {
            const int m = sp * 32 + wid * 2 + i;
            const size_t r = ((size_t)(b * M_ + m)) * (D_ / 4) + lane;
            const float4 va = unpack4(g_bagh[bstr + r]);        // C2
            const float4 vb = unpack4(g_bagh[2 * bstr + r]);    // C3
            float d = va.x * u4.x + va.y * u4.y + va.z * u4.z + va.w * u4.w;
            d = warpSum(d);
            const float e = __expf(d);
            if (lane == 0) out[(size_t)b * M_ + m] = d;         // prob_logit
            acc.x += e * vb.x; acc.y += e * vb.y;
            acc.z += e * vb.z; acc.w += e * vb.w;
            den += e;
        }
        reinterpret_cast<float4*>(&s_pt[wid][0])[lane] = acc;
        if (lane == 0) s_den[wid] = den;
    }
    __syncthreads();
    if (tid < D_) {
        float v = 0.f;
        #pragma unroll
        for (int k = 0; k < 16; k++) v += s_pt[k][tid];
        g_part2[((size_t)b * FSPL + sp) * D_ + tid] = v;
    }
    if (tid == 0) {
        float dn = 0.f;
        #pragma unroll
        for (int k = 0; k < 16; k++) dn += s_den[k];
        g_den2[b * FSPL + sp] = dn;
    }
    __syncthreads();

    // ---- last-arriver (mod-16, monotonic) computes final u3 -> OUT ----
    if (tid == 0) {
        __threadfence();
        const unsigned a = atomicAdd(&g_tC[b], 1u) + 1u;
        s_last = ((a % FSPL) == 0u);
    }
    __syncthreads();
    if (s_last) {
        __threadfence();   // acquire peers' partial writes
        if (tid < D_) {
            float dn = 0.f;
            #pragma unroll
            for (int k = 0; k < FSPL; k++) dn += g_den2[b * FSPL + k];
            float num = 0.f;
            #pragma unroll
            for (int k = 0; k < FSPL; k++) num += g_part2[((size_t)b * FSPL + k) * D_ + tid];
            out[(size_t)B_ * M_ + (size_t)b * D_ + tid] = s_u[tid] + num / dn;
        }
    }
}

extern "C" void kernel_launch(void* const* d_in, const int* in_sizes, int n_in,
                              void* d_out, int out_size)
{
    const int*   story  = (const int*)  d_in[0];   // [B, M, S] int32
    const float* hidden = (const float*)d_in[1];   // [B, 1, D] f32
    const float* C      = (const float*)d_in[2];   // [4, V, D] f32
    float* out = (float*)d_out;                    // [B*M] logits ++ [B*D] u

    k_all<<<GBLK + FBLK, 512>>>(story, hidden, C, out);   // one launch
}